// round 11
// baseline (speedup 1.0000x reference)
#include <cuda_runtime.h>
typedef unsigned long long ull;

#define TT 128
#define ZD 32
#define KG4 74
#define KGP 300   // xh row stride (floats): a 0..7 | z 8..39 | h 40..295
#define US 132
#define ZS 68
#define NT 1024

__device__ __align__(16) float Wg_perm[KG4 * 1024 * 4];  // [k4][1024 rows][4]
__device__ __align__(16) float W1_perm[64 * 128 * 4];
__device__ __align__(16) float W2_perm[32 * 128 * 4];
__device__ __align__(16) float Wz_perm[32 * 64 * 4];

__device__ __forceinline__ void fma2(ull &d, ull a, ull b) {
    asm("fma.rn.f32x2 %0, %1, %2, %0;" : "+l"(d) : "l"(a), "l"(b));
}
__device__ __forceinline__ float hsum2(ull v) {
    float lo, hi; asm("mov.b64 {%0, %1}, %2;" : "=f"(lo), "=f"(hi) : "l"(v));
    return lo + hi;
}
__device__ __forceinline__ float fsig(float x) { return 1.f / (1.f + __expf(-x)); }
__device__ __forceinline__ float ftanh_(float x) { return fmaf(2.f, fsig(2.f * x), -1.f); }

__global__ void permute_weights(const float* __restrict__ W_ih, const float* __restrict__ W_hh,
                                const float* __restrict__ W1, const float* __restrict__ W2,
                                const float* __restrict__ Wz)
{
    const int stride = gridDim.x * blockDim.x;
    const int tid = blockIdx.x * blockDim.x + threadIdx.x;
    for (int i = tid; i < KG4 * 1024 * 4; i += stride) {
        int j = i & 3, R = (i >> 2) & 1023, k4 = i >> 12;
        int k = 4 * k4 + j;
        Wg_perm[i] = (k < 40) ? W_ih[R * 40 + k] : W_hh[R * 256 + (k - 40)];
    }
    for (int i = tid; i < 64 * 128 * 4; i += stride) {
        int j = i & 3, m = (i >> 2) & 127, k4 = i >> 9;
        W1_perm[i] = W1[m * 256 + 4 * k4 + j];
    }
    for (int i = tid; i < 32 * 128 * 4; i += stride) {
        int j = i & 3, m = (i >> 2) & 127, k4 = i >> 9;
        W2_perm[i] = W2[m * 128 + 4 * k4 + j];
    }
    for (int i = tid; i < 32 * 64 * 4; i += stride) {
        int j = i & 3, m = (i >> 2) & 63, k4 = i >> 8;
        Wz_perm[i] = Wz[m * 128 + 4 * k4 + j];
    }
}

// 128 CTAs x 1024 threads (32 warps, occ 50%). Thread (hid=tid>>2, bq=tid&3):
// all 4 gates of `hid` for 2 batch rows {2bq, 2bq+1}.
__global__ void __launch_bounds__(NT, 1)
lstm_guide_kernel(const float* __restrict__ A, const float* __restrict__ eps,
                  const float* __restrict__ z0, const float* __restrict__ h0,
                  const float* __restrict__ c0, const float* __restrict__ b_ih,
                  const float* __restrict__ b_hh, const float* __restrict__ b1,
                  const float* __restrict__ b2, const float* __restrict__ bz,
                  float* __restrict__ Z)
{
    __shared__ __align__(16) float xh[2 * 8 * KGP];
    __shared__ __align__(16) float u1s[8 * US];
    __shared__ __align__(16) float u2s[8 * US];
    __shared__ __align__(16) float zzs[8 * ZS];

    const int tid = threadIdx.x;
    const int n0 = blockIdx.x * 8;
    const int hid = tid >> 2, bq = tid & 3;

    const float bs0 = b_ih[hid]       + b_hh[hid];
    const float bs1 = b_ih[256 + hid] + b_hh[256 + hid];
    const float bs2 = b_ih[512 + hid] + b_hh[512 + hid];
    const float bs3 = b_ih[768 + hid] + b_hh[768 + hid];
    const int  m8 = tid >> 3, r8 = tid & 7;        // MLP roles
    const float b1v = b1[m8 & 127], b2v = b2[m8 & 127];

    for (int i = tid; i < 8 * 256; i += NT) {       // h0 -> buf0
        int b = i >> 8, k = i & 255;
        xh[b * KGP + 40 + k] = h0[k];
    }
    if (tid < 64) {                                 // a0
        int b = tid >> 3, k = tid & 7;
        xh[b * KGP + k] = A[((n0 + b) * TT) * 8 + k];
    } else if (tid < 320) {                         // z0
        int i = tid - 64, b = i >> 5, j = i & 31;
        xh[b * KGP + 8 + j] = z0[j];
    }
    float c_reg[2];
    c_reg[0] = c0[hid]; c_reg[1] = c0[hid];
    __syncthreads();

    const float* wb = Wg_perm + hid * 4;

    for (int t = 0; t < TT; ++t) {
        float* xc = xh + (t & 1) * 8 * KGP;
        float* xn = xh + ((t + 1) & 1) * 8 * KGP;

        // ===== gates: 4 gate rows (i,f,g,o of hid) x 2 batch rows =====
        ull acc[4][2];
        #pragma unroll
        for (int g = 0; g < 4; ++g) { acc[g][0] = 0ull; acc[g][1] = 0ull; }

        #pragma unroll 2
        for (int k4 = 0; k4 < KG4; ++k4) {
            const ulonglong2 w0 = __ldg((const ulonglong2*)(wb + (k4 * 1024 +   0) * 4));
            const ulonglong2 w1 = __ldg((const ulonglong2*)(wb + (k4 * 1024 + 256) * 4));
            const ulonglong2 w2 = __ldg((const ulonglong2*)(wb + (k4 * 1024 + 512) * 4));
            const ulonglong2 w3 = __ldg((const ulonglong2*)(wb + (k4 * 1024 + 768) * 4));
            #pragma unroll
            for (int j = 0; j < 2; ++j) {
                const ulonglong2 xv = *(const ulonglong2*)(xc + (2 * bq + j) * KGP + 4 * k4);
                fma2(acc[0][j], w0.x, xv.x); fma2(acc[0][j], w0.y, xv.y);
                fma2(acc[1][j], w1.x, xv.x); fma2(acc[1][j], w1.y, xv.y);
                fma2(acc[2][j], w2.x, xv.x); fma2(acc[2][j], w2.y, xv.y);
                fma2(acc[3][j], w3.x, xv.x); fma2(acc[3][j], w3.y, xv.y);
            }
        }

        // ===== LSTM cell =====
        #pragma unroll
        for (int j = 0; j < 2; ++j) {
            float iv = fsig(hsum2(acc[0][j]) + bs0);
            float fv = fsig(hsum2(acc[1][j]) + bs1);
            float gv = ftanh_(hsum2(acc[2][j]) + bs2);
            float ov = fsig(hsum2(acc[3][j]) + bs3);
            float c = fv * c_reg[j] + iv * gv;
            c_reg[j] = c;
            xn[(2 * bq + j) * KGP + 40 + hid] = ov * ftanh_(c);  // h -> next buffer
        }
        if (tid < 64 && t + 1 < TT) {               // a_{t+1} prefetch
            int b = tid >> 3, k = tid & 7;
            xn[b * KGP + k] = A[((n0 + b) * TT + t + 1) * 8 + k];
        }
        __syncthreads();                            // sync 1

        // ===== MLP1: thread (m=m8, r=r8): one output x one batch row =====
        {
            const float* xp = xn + r8 * KGP + 40;
            ull a0 = 0ull;
            #pragma unroll 4
            for (int k4 = 0; k4 < 64; ++k4) {
                const ulonglong2 wv = __ldg((const ulonglong2*)(W1_perm + ((k4 << 7) + m8) * 4));
                const ulonglong2 pv = *(const ulonglong2*)(xp + 4 * k4);
                fma2(a0, wv.x, pv.x); fma2(a0, wv.y, pv.y);
            }
            u1s[r8 * US + m8] = fmaxf(hsum2(a0) + b1v, 0.f);
        }
        __syncthreads();                            // sync 2

        // ===== MLP2 =====
        {
            const float* xp = u1s + r8 * US;
            ull a0 = 0ull;
            #pragma unroll 4
            for (int k4 = 0; k4 < 32; ++k4) {
                const ulonglong2 wv = __ldg((const ulonglong2*)(W2_perm + ((k4 << 7) + m8) * 4));
                const ulonglong2 pv = *(const ulonglong2*)(xp + 4 * k4);
                fma2(a0, wv.x, pv.x); fma2(a0, wv.y, pv.y);
            }
            u2s[r8 * US + m8] = fmaxf(hsum2(a0) + b2v, 0.f);
        }
        __syncthreads();                            // sync 3

        // ===== zz = u2 @ Wz^T + bz  (first 512 threads: 64 j x 8 r) =====
        if (tid < 512) {
            const int jz = tid >> 3, rz = tid & 7;
            const float* xp = u2s + rz * US;
            ull a0 = 0ull;
            #pragma unroll 4
            for (int k4 = 0; k4 < 32; ++k4) {
                const ulonglong2 wv = __ldg((const ulonglong2*)(Wz_perm + ((k4 << 6) + jz) * 4));
                const ulonglong2 pv = *(const ulonglong2*)(xp + 4 * k4);
                fma2(a0, wv.x, pv.x); fma2(a0, wv.y, pv.y);
            }
            zzs[rz * ZS + jz] = hsum2(a0) + bz[jz];
        }
        __syncthreads();                            // sync 4

        // ===== z_t = loc + softplus(raw) * eps =====
        if (tid < 256) {
            const int j = tid & 31, r = tid >> 5;
            float loc = zzs[r * ZS + j];
            float sr  = zzs[r * ZS + 32 + j];
            float sp  = (sr > 15.f) ? sr : log1pf(__expf(sr));
            float e   = eps[((n0 + r) * TT + t) * ZD + j];
            float zn  = fmaf(sp, e, loc);
            Z[((n0 + r) * TT + t) * ZD + j] = zn;
            xn[r * KGP + 8 + j] = zn;
        }
        __syncthreads();                            // sync 5
    }
}

extern "C" void kernel_launch(void* const* d_in, const int* in_sizes, int n_in,
                              void* d_out, int out_size) {
    const float* A    = (const float*)d_in[0];
    const float* eps  = (const float*)d_in[1];
    const float* z0   = (const float*)d_in[2];
    const float* h0   = (const float*)d_in[3];
    const float* c0   = (const float*)d_in[4];
    const float* W_ih = (const float*)d_in[5];
    const float* W_hh = (const float*)d_in[6];
    const float* b_ih = (const float*)d_in[7];
    const float* b_hh = (const float*)d_in[8];
    const float* W1   = (const float*)d_in[9];
    const float* b1   = (const float*)d_in[10];
    const float* W2   = (const float*)d_in[11];
    const float* b2   = (const float*)d_in[12];
    const float* Wz   = (const float*)d_in[13];
    const float* bz   = (const float*)d_in[14];

    permute_weights<<<148, 256>>>(W_ih, W_hh, W1, W2, Wz);
    lstm_guide_kernel<<<128, NT>>>(A, eps, z0, h0, c0,
                                   b_ih, b_hh, b1, b2, bz, (float*)d_out);
}

// round 12
// speedup vs baseline: 1.5051x; 1.5051x over previous
#include <cuda_runtime.h>
typedef unsigned long long ull;

#define TT 128
#define ZD 32
#define KG4 74
#define KGP 300   // xh row stride (floats): a 0..7 | z 8..39 | h 40..295
#define US 132
#define ZS 68
#define NT 512

__device__ __align__(16) float Wg_perm[KG4 * 1024 * 4];  // [k4][1024 rows][4]
__device__ __align__(16) float W1_perm[64 * 128 * 4];
__device__ __align__(16) float W2_perm[32 * 128 * 4];
__device__ __align__(16) float Wz_perm[32 * 64 * 4];

__device__ __forceinline__ void fma2(ull &d, ull a, ull b) {
    asm("fma.rn.f32x2 %0, %1, %2, %0;" : "+l"(d) : "l"(a), "l"(b));
}
__device__ __forceinline__ float hsum2(ull v) {
    float lo, hi; asm("mov.b64 {%0, %1}, %2;" : "=f"(lo), "=f"(hi) : "l"(v));
    return lo + hi;
}
__device__ __forceinline__ float fsig(float x) { return 1.f / (1.f + __expf(-x)); }
__device__ __forceinline__ float ftanh_(float x) { return fmaf(2.f, fsig(2.f * x), -1.f); }

__global__ void permute_weights(const float* __restrict__ W_ih, const float* __restrict__ W_hh,
                                const float* __restrict__ W1, const float* __restrict__ W2,
                                const float* __restrict__ Wz)
{
    const int stride = gridDim.x * blockDim.x;
    const int tid = blockIdx.x * blockDim.x + threadIdx.x;
    for (int i = tid; i < KG4 * 1024 * 4; i += stride) {
        int j = i & 3, R = (i >> 2) & 1023, k4 = i >> 12;
        int k = 4 * k4 + j;
        Wg_perm[i] = (k < 40) ? W_ih[R * 40 + k] : W_hh[R * 256 + (k - 40)];
    }
    for (int i = tid; i < 64 * 128 * 4; i += stride) {
        int j = i & 3, m = (i >> 2) & 127, k4 = i >> 9;
        W1_perm[i] = W1[m * 256 + 4 * k4 + j];
    }
    for (int i = tid; i < 32 * 128 * 4; i += stride) {
        int j = i & 3, m = (i >> 2) & 127, k4 = i >> 9;
        W2_perm[i] = W2[m * 128 + 4 * k4 + j];
    }
    for (int i = tid; i < 32 * 64 * 4; i += stride) {
        int j = i & 3, m = (i >> 2) & 63, k4 = i >> 8;
        Wz_perm[i] = Wz[m * 128 + 4 * k4 + j];
    }
}

// One CTA = 8 batch rows, 512 threads. Gate thread (hid=tid>>1, bq=tid&1):
// all 4 gates of `hid` x 4 batch rows. MLP thread (m=tid>>2, rq=tid&3):
// output m for rows {rq, rq+4} — 1-line weight LDGs. zz thread (j=tid>>3, r=tid&7).
__global__ void __launch_bounds__(NT, 1)
lstm_guide_kernel(const float* __restrict__ A, const float* __restrict__ eps,
                  const float* __restrict__ z0, const float* __restrict__ h0,
                  const float* __restrict__ c0, const float* __restrict__ b_ih,
                  const float* __restrict__ b_hh, const float* __restrict__ b1,
                  const float* __restrict__ b2, const float* __restrict__ bz,
                  float* __restrict__ Z)
{
    __shared__ __align__(16) float xh[2 * 8 * KGP];
    __shared__ __align__(16) float u1s[8 * US];
    __shared__ __align__(16) float u2s[8 * US];
    __shared__ __align__(16) float zzs[8 * ZS];

    const int tid = threadIdx.x;
    const int n0 = blockIdx.x * 8;
    const int hid = tid >> 1, bq = tid & 1;
    const int mM = tid >> 2, rq = tid & 3;          // MLP roles
    const int jz = tid >> 3, rz = tid & 7;          // zz roles

    const float bs0 = b_ih[hid]       + b_hh[hid];
    const float bs1 = b_ih[256 + hid] + b_hh[256 + hid];
    const float bs2 = b_ih[512 + hid] + b_hh[512 + hid];
    const float bs3 = b_ih[768 + hid] + b_hh[768 + hid];
    const float b1v = b1[mM], b2v = b2[mM], bzv = bz[jz];

    for (int i = tid; i < 8 * 256; i += NT) {       // h0 -> buf0
        int b = i >> 8, k = i & 255;
        xh[b * KGP + 40 + k] = h0[k];
    }
    if (tid < 64) {                                 // a0
        int b = tid >> 3, k = tid & 7;
        xh[b * KGP + k] = A[((n0 + b) * TT) * 8 + k];
    } else if (tid < 320) {                         // z0
        int i = tid - 64, b = i >> 5, j = i & 31;
        xh[b * KGP + 8 + j] = z0[j];
    }
    float c_reg[4];
    #pragma unroll
    for (int j = 0; j < 4; ++j) c_reg[j] = c0[hid];
    __syncthreads();

    const float* wb = Wg_perm + hid * 4;

    for (int t = 0; t < TT; ++t) {
        float* xc = xh + (t & 1) * 8 * KGP;
        float* xn = xh + ((t + 1) & 1) * 8 * KGP;

        // ===== gates: 4 rows (i,f,g,o of hid) x 4 batch (b = bq*4+j) =====
        ull acc[4][4];
        #pragma unroll
        for (int g = 0; g < 4; ++g)
            #pragma unroll
            for (int j = 0; j < 4; ++j) acc[g][j] = 0ull;

        #pragma unroll 2
        for (int k4 = 0; k4 < KG4; ++k4) {
            const ulonglong2 w0 = __ldg((const ulonglong2*)(wb + (k4 * 1024 +   0) * 4));
            const ulonglong2 w1 = __ldg((const ulonglong2*)(wb + (k4 * 1024 + 256) * 4));
            const ulonglong2 w2 = __ldg((const ulonglong2*)(wb + (k4 * 1024 + 512) * 4));
            const ulonglong2 w3 = __ldg((const ulonglong2*)(wb + (k4 * 1024 + 768) * 4));
            #pragma unroll
            for (int j = 0; j < 4; ++j) {
                const ulonglong2 xv = *(const ulonglong2*)(xc + (bq * 4 + j) * KGP + 4 * k4);
                fma2(acc[0][j], w0.x, xv.x); fma2(acc[0][j], w0.y, xv.y);
                fma2(acc[1][j], w1.x, xv.x); fma2(acc[1][j], w1.y, xv.y);
                fma2(acc[2][j], w2.x, xv.x); fma2(acc[2][j], w2.y, xv.y);
                fma2(acc[3][j], w3.x, xv.x); fma2(acc[3][j], w3.y, xv.y);
            }
        }

        // ===== LSTM cell =====
        #pragma unroll
        for (int j = 0; j < 4; ++j) {
            float iv = fsig(hsum2(acc[0][j]) + bs0);
            float fv = fsig(hsum2(acc[1][j]) + bs1);
            float gv = ftanh_(hsum2(acc[2][j]) + bs2);
            float ov = fsig(hsum2(acc[3][j]) + bs3);
            float c = fv * c_reg[j] + iv * gv;
            c_reg[j] = c;
            xn[(bq * 4 + j) * KGP + 40 + hid] = ov * ftanh_(c);  // h -> next buffer
        }
        if (tid < 64 && t + 1 < TT) {               // a_{t+1} prefetch
            int b = tid >> 3, k = tid & 7;
            xn[b * KGP + k] = A[((n0 + b) * TT + t + 1) * 8 + k];
        }
        __syncthreads();                            // sync 1

        // ===== MLP1: thread (mM, rq): rows rq and rq+4 — 1-line weight LDGs =====
        {
            const float* x0 = xn + rq * KGP + 40;
            const float* x1 = x0 + 4 * KGP;
            ull a0 = 0ull, a1 = 0ull;
            #pragma unroll 4
            for (int k4 = 0; k4 < 64; ++k4) {
                const ulonglong2 wv = __ldg((const ulonglong2*)(W1_perm + ((k4 << 7) + mM) * 4));
                const ulonglong2 p0 = *(const ulonglong2*)(x0 + 4 * k4);
                const ulonglong2 p1 = *(const ulonglong2*)(x1 + 4 * k4);
                fma2(a0, wv.x, p0.x); fma2(a0, wv.y, p0.y);
                fma2(a1, wv.x, p1.x); fma2(a1, wv.y, p1.y);
            }
            u1s[rq * US + mM]       = fmaxf(hsum2(a0) + b1v, 0.f);
            u1s[(rq + 4) * US + mM] = fmaxf(hsum2(a1) + b1v, 0.f);
        }
        __syncthreads();                            // sync 2

        // ===== MLP2 =====
        {
            const float* x0 = u1s + rq * US;
            const float* x1 = x0 + 4 * US;
            ull a0 = 0ull, a1 = 0ull;
            #pragma unroll 4
            for (int k4 = 0; k4 < 32; ++k4) {
                const ulonglong2 wv = __ldg((const ulonglong2*)(W2_perm + ((k4 << 7) + mM) * 4));
                const ulonglong2 p0 = *(const ulonglong2*)(x0 + 4 * k4);
                const ulonglong2 p1 = *(const ulonglong2*)(x1 + 4 * k4);
                fma2(a0, wv.x, p0.x); fma2(a0, wv.y, p0.y);
                fma2(a1, wv.x, p1.x); fma2(a1, wv.y, p1.y);
            }
            u2s[rq * US + mM]       = fmaxf(hsum2(a0) + b2v, 0.f);
            u2s[(rq + 4) * US + mM] = fmaxf(hsum2(a1) + b2v, 0.f);
        }
        __syncthreads();                            // sync 3

        // ===== zz: thread (jz, rz) — 1-line Wz LDGs, full-bank LDS =====
        {
            const float* xp = u2s + rz * US;
            ull a0 = 0ull;
            #pragma unroll 4
            for (int k4 = 0; k4 < 32; ++k4) {
                const ulonglong2 wv = __ldg((const ulonglong2*)(Wz_perm + ((k4 << 6) + jz) * 4));
                const ulonglong2 pv = *(const ulonglong2*)(xp + 4 * k4);
                fma2(a0, wv.x, pv.x); fma2(a0, wv.y, pv.y);
            }
            zzs[rz * ZS + jz] = hsum2(a0) + bzv;
        }
        __syncthreads();                            // sync 4

        // ===== z_t = loc + softplus(raw) * eps =====
        if (tid < 256) {
            const int j = tid & 31, r = tid >> 5;
            float loc = zzs[r * ZS + j];
            float sr  = zzs[r * ZS + 32 + j];
            float sp  = (sr > 15.f) ? sr : log1pf(__expf(sr));
            float e   = eps[((n0 + r) * TT + t) * ZD + j];
            float zn  = fmaf(sp, e, loc);
            Z[((n0 + r) * TT + t) * ZD + j] = zn;
            xn[r * KGP + 8 + j] = zn;
        }
        __syncthreads();                            // sync 5
    }
}

extern "C" void kernel_launch(void* const* d_in, const int* in_sizes, int n_in,
                              void* d_out, int out_size) {
    const float* A    = (const float*)d_in[0];
    const float* eps  = (const float*)d_in[1];
    const float* z0   = (const float*)d_in[2];
    const float* h0   = (const float*)d_in[3];
    const float* c0   = (const float*)d_in[4];
    const float* W_ih = (const float*)d_in[5];
    const float* W_hh = (const float*)d_in[6];
    const float* b_ih = (const float*)d_in[7];
    const float* b_hh = (const float*)d_in[8];
    const float* W1   = (const float*)d_in[9];
    const float* b1   = (const float*)d_in[10];
    const float* W2   = (const float*)d_in[11];
    const float* b2   = (const float*)d_in[12];
    const float* Wz   = (const float*)d_in[13];
    const float* bz   = (const float*)d_in[14];

    permute_weights<<<148, 256>>>(W_ih, W_hh, W1, W2, Wz);
    lstm_guide_kernel<<<128, NT>>>(A, eps, z0, h0, c0,
                                   b_ih, b_hh, b1, b2, bz, (float*)d_out);
}

// round 13
// speedup vs baseline: 1.5163x; 1.0074x over previous
#include <cuda_runtime.h>
typedef unsigned long long ull;

#define TT 128
#define ZD 32
#define KG4 74
#define KGP 300   // xh row stride (floats): a 0..7 | z 8..39 | h 40..295
#define US 132
#define ZS 68
#define NT 512

__device__ __align__(16) float Wg_perm[KG4 * 1024 * 4];  // [k4][1024 rows][4]
__device__ __align__(16) float W1_perm[64 * 128 * 4];
__device__ __align__(16) float W2_perm[32 * 128 * 4];
__device__ __align__(16) float Wz_perm[32 * 64 * 4];

__device__ __forceinline__ void fma2(ull &d, ull a, ull b) {
    asm("fma.rn.f32x2 %0, %1, %2, %0;" : "+l"(d) : "l"(a), "l"(b));
}
__device__ __forceinline__ float hsum2(ull v) {
    float lo, hi; asm("mov.b64 {%0, %1}, %2;" : "=f"(lo), "=f"(hi) : "l"(v));
    return lo + hi;
}
__device__ __forceinline__ float fsig(float x) { return 1.f / (1.f + __expf(-x)); }
__device__ __forceinline__ float ftanh_(float x) { return fmaf(2.f, fsig(2.f * x), -1.f); }

#define BARS(id, cnt) asm volatile("bar.sync %0, %1;"   :: "r"(id), "r"(cnt) : "memory")
#define BARA(id, cnt) asm volatile("bar.arrive %0, %1;" :: "r"(id), "r"(cnt) : "memory")
// barrier ids: 1=H (h ready), 2=Z (z+a ready), 3=G (gate-internal), 4=M (mlp-internal)

__global__ void permute_weights(const float* __restrict__ W_ih, const float* __restrict__ W_hh,
                                const float* __restrict__ W1, const float* __restrict__ W2,
                                const float* __restrict__ Wz)
{
    const int stride = gridDim.x * blockDim.x;
    const int tid = blockIdx.x * blockDim.x + threadIdx.x;
    for (int i = tid; i < KG4 * 1024 * 4; i += stride) {
        int j = i & 3, R = (i >> 2) & 1023, k4 = i >> 12;
        int k = 4 * k4 + j;
        Wg_perm[i] = (k < 40) ? W_ih[R * 40 + k] : W_hh[R * 256 + (k - 40)];
    }
    for (int i = tid; i < 64 * 128 * 4; i += stride) {
        int j = i & 3, m = (i >> 2) & 127, k4 = i >> 9;
        W1_perm[i] = W1[m * 256 + 4 * k4 + j];
    }
    for (int i = tid; i < 32 * 128 * 4; i += stride) {
        int j = i & 3, m = (i >> 2) & 127, k4 = i >> 9;
        W2_perm[i] = W2[m * 128 + 4 * k4 + j];
    }
    for (int i = tid; i < 32 * 64 * 4; i += stride) {
        int j = i & 3, m = (i >> 2) & 63, k4 = i >> 8;
        Wz_perm[i] = Wz[m * 128 + 4 * k4 + j];
    }
}

#define GSTEP(c4) do { \
    const ulonglong2 w0 = __ldg((const ulonglong2*)(wb + ((c4) * 1024 +   0) * 4)); \
    const ulonglong2 w1 = __ldg((const ulonglong2*)(wb + ((c4) * 1024 + 256) * 4)); \
    const ulonglong2 w2 = __ldg((const ulonglong2*)(wb + ((c4) * 1024 + 512) * 4)); \
    const ulonglong2 w3 = __ldg((const ulonglong2*)(wb + ((c4) * 1024 + 768) * 4)); \
    _Pragma("unroll") \
    for (int b = 0; b < 8; ++b) { \
        const ulonglong2 xv = *(const ulonglong2*)(xc + b * KGP + 4 * (c4)); \
        fma2(acc0[b], w0.x, xv.x); fma2(acc0[b], w0.y, xv.y); \
        fma2(acc1[b], w1.x, xv.x); fma2(acc1[b], w1.y, xv.y); \
        fma2(acc2[b], w2.x, xv.x); fma2(acc2[b], w2.y, xv.y); \
        fma2(acc3[b], w3.x, xv.x); fma2(acc3[b], w3.y, xv.y); \
    } \
} while (0)

// Warp-specialized: warps 0-7 = gates (thread hid=tid: 4 gates x 8 batch),
// warps 8-15 = MLP chain + a-prefetch. Gates overlap their h-part of step t
// with the MLP chain of step t-1; z needed only for the last 10 k-chunks.
__global__ void __launch_bounds__(NT, 1)
lstm_guide_kernel(const float* __restrict__ A, const float* __restrict__ eps,
                  const float* __restrict__ z0, const float* __restrict__ h0,
                  const float* __restrict__ c0, const float* __restrict__ b_ih,
                  const float* __restrict__ b_hh, const float* __restrict__ b1,
                  const float* __restrict__ b2, const float* __restrict__ bz,
                  float* __restrict__ Z)
{
    __shared__ __align__(16) float xh[2 * 8 * KGP];
    __shared__ __align__(16) float u1s[8 * US];
    __shared__ __align__(16) float u2s[8 * US];
    __shared__ __align__(16) float zzs[8 * ZS];

    const int tid = threadIdx.x;
    const int n0 = blockIdx.x * 8;

    // ---- init: x(0) = [a0 | z0 | h0] into buffer 0 ----
    for (int i = tid; i < 8 * 256; i += NT) {
        int b = i >> 8, k = i & 255;
        xh[b * KGP + 40 + k] = h0[k];
    }
    if (tid < 64) {
        int b = tid >> 3, k = tid & 7;
        xh[b * KGP + k] = A[((n0 + b) * TT) * 8 + k];
    } else if (tid < 320) {
        int i = tid - 64, b = i >> 5, j = i & 31;
        xh[b * KGP + 8 + j] = z0[j];
    }
    __syncthreads();

    if (tid < 256) {
        // ================= GATE GROUP =================
        const int hid = tid;
        const float bs0 = b_ih[hid]       + b_hh[hid];
        const float bs1 = b_ih[256 + hid] + b_hh[256 + hid];
        const float bs2 = b_ih[512 + hid] + b_hh[512 + hid];
        const float bs3 = b_ih[768 + hid] + b_hh[768 + hid];
        const float* wb = Wg_perm + hid * 4;
        float c_reg[8];
        #pragma unroll
        for (int b = 0; b < 8; ++b) c_reg[b] = c0[hid];

        for (int t = 0; t < TT; ++t) {
            const float* xc = xh + (t & 1) * 8 * KGP;
            float* xn = xh + ((t + 1) & 1) * 8 * KGP;

            ull acc0[8], acc1[8], acc2[8], acc3[8];
            #pragma unroll
            for (int b = 0; b < 8; ++b) { acc0[b]=0; acc1[b]=0; acc2[b]=0; acc3[b]=0; }

            // h-part (cols 40..295): needs only previous gate output (G-synced)
            #pragma unroll 2
            for (int c4 = 10; c4 < KG4; ++c4) GSTEP(c4);

            BARS(2, 512);   // wait z(t-1) + a(t) from MLP group (pre-armed at t=0)

            // a+z part (cols 0..39)
            #pragma unroll 2
            for (int c4 = 0; c4 < 10; ++c4) GSTEP(c4);

            // cell + h(t+1) -> next buffer
            #pragma unroll
            for (int b = 0; b < 8; ++b) {
                float iv = fsig(hsum2(acc0[b]) + bs0);
                float fv = fsig(hsum2(acc1[b]) + bs1);
                float gv = ftanh_(hsum2(acc2[b]) + bs2);
                float ov = fsig(hsum2(acc3[b]) + bs3);
                float c = fv * c_reg[b] + iv * gv;
                c_reg[b] = c;
                xn[b * KGP + 40 + hid] = ov * ftanh_(c);
            }
            BARA(1, 512);   // h(t+1) ready -> release MLP group
            BARS(3, 256);   // gate-internal: all h writes visible to gate group
        }
    } else {
        // ================= MLP GROUP =================
        const int t2 = tid - 256;
        const int mM = t2 & 127, q4 = (t2 >> 7) * 4;     // MLP rows q4..q4+3
        const int j64 = t2 & 63, u2r = (t2 >> 6) * 2;    // zz rows u2r, u2r+1
        const int jf = t2 & 31, rf = t2 >> 5;            // final z task
        const float b1v = b1[mM], b2v = b2[mM];
        const float bzv = bz[j64];

        BARA(2, 512);   // pre-arm Z: x(0) already holds z0 + a0

        for (int t = 0; t < TT; ++t) {
            float* xn = xh + ((t + 1) & 1) * 8 * KGP;

            BARS(1, 512);   // wait h(t+1)

            // a(t+1) prefetch into xn
            if (t2 < 64 && t + 1 < TT) {
                int b = t2 >> 3, k = t2 & 7;
                xn[b * KGP + k] = A[((n0 + b) * TT + t + 1) * 8 + k];
            }

            // MLP1: output mM for rows q4..q4+3
            {
                ull a0=0, a1=0, a2=0, a3=0;
                const float* x0 = xn + q4 * KGP + 40;
                #pragma unroll 4
                for (int k4 = 0; k4 < 64; ++k4) {
                    const ulonglong2 wv = __ldg((const ulonglong2*)(W1_perm + ((k4 << 7) + mM) * 4));
                    const ulonglong2 p0 = *(const ulonglong2*)(x0 + 4 * k4);
                    const ulonglong2 p1 = *(const ulonglong2*)(x0 + KGP + 4 * k4);
                    const ulonglong2 p2 = *(const ulonglong2*)(x0 + 2 * KGP + 4 * k4);
                    const ulonglong2 p3 = *(const ulonglong2*)(x0 + 3 * KGP + 4 * k4);
                    fma2(a0, wv.x, p0.x); fma2(a0, wv.y, p0.y);
                    fma2(a1, wv.x, p1.x); fma2(a1, wv.y, p1.y);
                    fma2(a2, wv.x, p2.x); fma2(a2, wv.y, p2.y);
                    fma2(a3, wv.x, p3.x); fma2(a3, wv.y, p3.y);
                }
                u1s[q4 * US + mM]       = fmaxf(hsum2(a0) + b1v, 0.f);
                u1s[(q4 + 1) * US + mM] = fmaxf(hsum2(a1) + b1v, 0.f);
                u1s[(q4 + 2) * US + mM] = fmaxf(hsum2(a2) + b1v, 0.f);
                u1s[(q4 + 3) * US + mM] = fmaxf(hsum2(a3) + b1v, 0.f);
            }
            BARS(4, 256);

            // MLP2
            {
                ull a0=0, a1=0, a2=0, a3=0;
                const float* x0 = u1s + q4 * US;
                #pragma unroll 4
                for (int k4 = 0; k4 < 32; ++k4) {
                    const ulonglong2 wv = __ldg((const ulonglong2*)(W2_perm + ((k4 << 7) + mM) * 4));
                    const ulonglong2 p0 = *(const ulonglong2*)(x0 + 4 * k4);
                    const ulonglong2 p1 = *(const ulonglong2*)(x0 + US + 4 * k4);
                    const ulonglong2 p2 = *(const ulonglong2*)(x0 + 2 * US + 4 * k4);
                    const ulonglong2 p3 = *(const ulonglong2*)(x0 + 3 * US + 4 * k4);
                    fma2(a0, wv.x, p0.x); fma2(a0, wv.y, p0.y);
                    fma2(a1, wv.x, p1.x); fma2(a1, wv.y, p1.y);
                    fma2(a2, wv.x, p2.x); fma2(a2, wv.y, p2.y);
                    fma2(a3, wv.x, p3.x); fma2(a3, wv.y, p3.y);
                }
                u2s[q4 * US + mM]       = fmaxf(hsum2(a0) + b2v, 0.f);
                u2s[(q4 + 1) * US + mM] = fmaxf(hsum2(a1) + b2v, 0.f);
                u2s[(q4 + 2) * US + mM] = fmaxf(hsum2(a2) + b2v, 0.f);
                u2s[(q4 + 3) * US + mM] = fmaxf(hsum2(a3) + b2v, 0.f);
            }
            BARS(4, 256);

            // zz: output j64 for rows u2r, u2r+1
            {
                ull a0 = 0, a1 = 0;
                const float* x0 = u2s + u2r * US;
                #pragma unroll 4
                for (int k4 = 0; k4 < 32; ++k4) {
                    const ulonglong2 wv = __ldg((const ulonglong2*)(Wz_perm + ((k4 << 6) + j64) * 4));
                    const ulonglong2 p0 = *(const ulonglong2*)(x0 + 4 * k4);
                    const ulonglong2 p1 = *(const ulonglong2*)(x0 + US + 4 * k4);
                    fma2(a0, wv.x, p0.x); fma2(a0, wv.y, p0.y);
                    fma2(a1, wv.x, p1.x); fma2(a1, wv.y, p1.y);
                }
                zzs[u2r * ZS + j64]       = hsum2(a0) + bzv;
                zzs[(u2r + 1) * ZS + j64] = hsum2(a1) + bzv;
            }
            BARS(4, 256);

            // z_t = loc + softplus(raw) * eps; -> global Z and xn z-cols
            {
                float loc = zzs[rf * ZS + jf];
                float sr  = zzs[rf * ZS + 32 + jf];
                float sp  = (sr > 15.f) ? sr : log1pf(__expf(sr));
                float e   = eps[((n0 + rf) * TT + t) * ZD + jf];
                float zn  = fmaf(sp, e, loc);
                Z[((n0 + rf) * TT + t) * ZD + jf] = zn;
                xn[rf * KGP + 8 + jf] = zn;
            }
            BARA(2, 512);   // z(t) + a(t+1) ready -> release gates' next z-part
        }
    }
}

extern "C" void kernel_launch(void* const* d_in, const int* in_sizes, int n_in,
                              void* d_out, int out_size) {
    const float* A    = (const float*)d_in[0];
    const float* eps  = (const float*)d_in[1];
    const float* z0   = (const float*)d_in[2];
    const float* h0   = (const float*)d_in[3];
    const float* c0   = (const float*)d_in[4];
    const float* W_ih = (const float*)d_in[5];
    const float* W_hh = (const float*)d_in[6];
    const float* b_ih = (const float*)d_in[7];
    const float* b_hh = (const float*)d_in[8];
    const float* W1   = (const float*)d_in[9];
    const float* b1   = (const float*)d_in[10];
    const float* W2   = (const float*)d_in[11];
    const float* b2   = (const float*)d_in[12];
    const float* Wz   = (const float*)d_in[13];
    const float* bz   = (const float*)d_in[14];

    permute_weights<<<148, 256>>>(W_ih, W_hh, W1, W2, Wz);
    lstm_guide_kernel<<<128, NT>>>(A, eps, z0, h0, c0,
                                   b_ih, b_hh, b1, b2, bz, (float*)d_out);
}

// round 14
// speedup vs baseline: 1.6259x; 1.0723x over previous
#include <cuda_runtime.h>
typedef unsigned long long ull;

#define TT 128
#define ZD 32
#define KG4 74
#define KGP 300   // xh row stride (floats): a 0..7 | z 8..39 | h 40..295
#define US 132
#define ZS 68
#define NT 768    // 512 gate + 256 MLP

__device__ __align__(16) float Wg_perm[KG4 * 1024 * 4];  // [k4][1024 rows][4]
__device__ __align__(16) float W1_perm[64 * 128 * 4];
__device__ __align__(16) float W2_perm[32 * 128 * 4];
__device__ __align__(16) float Wz_perm[32 * 64 * 4];

__device__ __forceinline__ void fma2(ull &d, ull a, ull b) {
    asm("fma.rn.f32x2 %0, %1, %2, %0;" : "+l"(d) : "l"(a), "l"(b));
}
__device__ __forceinline__ float hsum2(ull v) {
    float lo, hi; asm("mov.b64 {%0, %1}, %2;" : "=f"(lo), "=f"(hi) : "l"(v));
    return lo + hi;
}
__device__ __forceinline__ float fsig(float x) { return 1.f / (1.f + __expf(-x)); }
__device__ __forceinline__ float ftanh_(float x) { return fmaf(2.f, fsig(2.f * x), -1.f); }

#define BARS(id, cnt) asm volatile("bar.sync %0, %1;"   :: "r"(id), "r"(cnt) : "memory")
#define BARA(id, cnt) asm volatile("bar.arrive %0, %1;" :: "r"(id), "r"(cnt) : "memory")
// ids: 1=H (h ready; gates arrive, MLP sync), 2=Z (z+a ready; MLP arrive, gates sync),
//      3=gate-internal, 4=MLP-internal

__global__ void permute_weights(const float* __restrict__ W_ih, const float* __restrict__ W_hh,
                                const float* __restrict__ W1, const float* __restrict__ W2,
                                const float* __restrict__ Wz)
{
    const int stride = gridDim.x * blockDim.x;
    const int tid = blockIdx.x * blockDim.x + threadIdx.x;
    for (int i = tid; i < KG4 * 1024 * 4; i += stride) {
        int j = i & 3, R = (i >> 2) & 1023, k4 = i >> 12;
        int k = 4 * k4 + j;
        Wg_perm[i] = (k < 40) ? W_ih[R * 40 + k] : W_hh[R * 256 + (k - 40)];
    }
    for (int i = tid; i < 64 * 128 * 4; i += stride) {
        int j = i & 3, m = (i >> 2) & 127, k4 = i >> 9;
        W1_perm[i] = W1[m * 256 + 4 * k4 + j];
    }
    for (int i = tid; i < 32 * 128 * 4; i += stride) {
        int j = i & 3, m = (i >> 2) & 127, k4 = i >> 9;
        W2_perm[i] = W2[m * 128 + 4 * k4 + j];
    }
    for (int i = tid; i < 32 * 64 * 4; i += stride) {
        int j = i & 3, m = (i >> 2) & 63, k4 = i >> 8;
        Wz_perm[i] = Wz[m * 128 + 4 * k4 + j];
    }
}

#define GSTEP(c4) do { \
    const ulonglong2 w0 = __ldg((const ulonglong2*)(wb + ((c4) * 1024 +   0) * 4)); \
    const ulonglong2 w1 = __ldg((const ulonglong2*)(wb + ((c4) * 1024 + 256) * 4)); \
    const ulonglong2 w2 = __ldg((const ulonglong2*)(wb + ((c4) * 1024 + 512) * 4)); \
    const ulonglong2 w3 = __ldg((const ulonglong2*)(wb + ((c4) * 1024 + 768) * 4)); \
    _Pragma("unroll") \
    for (int j = 0; j < 4; ++j) { \
        const ulonglong2 xv = *(const ulonglong2*)(xc + (bq * 4 + j) * KGP + 4 * (c4)); \
        fma2(acc0[j], w0.x, xv.x); fma2(acc0[j], w0.y, xv.y); \
        fma2(acc1[j], w1.x, xv.x); fma2(acc1[j], w1.y, xv.y); \
        fma2(acc2[j], w2.x, xv.x); fma2(acc2[j], w2.y, xv.y); \
        fma2(acc3[j], w3.x, xv.x); fma2(acc3[j], w3.y, xv.y); \
    } \
} while (0)

// 768 threads: tid<512 = gate group (hid=tid>>1, bq=tid&1: 4 gates x 4 batch,
// round-7 tile, no spills). tid>=512 = MLP group (full chain + a-prefetch).
// Gates overlap the h-part of step t with the MLP chain of step t-1.
__global__ void __launch_bounds__(NT, 1)
lstm_guide_kernel(const float* __restrict__ A, const float* __restrict__ eps,
                  const float* __restrict__ z0, const float* __restrict__ h0,
                  const float* __restrict__ c0, const float* __restrict__ b_ih,
                  const float* __restrict__ b_hh, const float* __restrict__ b1,
                  const float* __restrict__ b2, const float* __restrict__ bz,
                  float* __restrict__ Z)
{
    __shared__ __align__(16) float xh[2 * 8 * KGP];
    __shared__ __align__(16) float u1s[8 * US];
    __shared__ __align__(16) float u2s[8 * US];
    __shared__ __align__(16) float zzs[8 * ZS];

    const int tid = threadIdx.x;
    const int n0 = blockIdx.x * 8;

    // ---- init x(0) = [a0 | z0 | h0] into buffer 0 ----
    for (int i = tid; i < 8 * 256; i += NT) {
        int b = i >> 8, k = i & 255;
        xh[b * KGP + 40 + k] = h0[k];
    }
    if (tid < 64) {
        int b = tid >> 3, k = tid & 7;
        xh[b * KGP + k] = A[((n0 + b) * TT) * 8 + k];
    } else if (tid < 320) {
        int i = tid - 64, b = i >> 5, j = i & 31;
        xh[b * KGP + 8 + j] = z0[j];
    }
    __syncthreads();

    if (tid < 512) {
        // ================= GATE GROUP (512 threads) =================
        const int hid = tid >> 1, bq = tid & 1;
        const float bs0 = b_ih[hid]       + b_hh[hid];
        const float bs1 = b_ih[256 + hid] + b_hh[256 + hid];
        const float bs2 = b_ih[512 + hid] + b_hh[512 + hid];
        const float bs3 = b_ih[768 + hid] + b_hh[768 + hid];
        const float* wb = Wg_perm + hid * 4;
        float c_reg[4];
        #pragma unroll
        for (int j = 0; j < 4; ++j) c_reg[j] = c0[hid];

        for (int t = 0; t < TT; ++t) {
            const float* xc = xh + (t & 1) * 8 * KGP;
            float* xn = xh + ((t + 1) & 1) * 8 * KGP;

            ull acc0[4], acc1[4], acc2[4], acc3[4];
            #pragma unroll
            for (int j = 0; j < 4; ++j) { acc0[j]=0; acc1[j]=0; acc2[j]=0; acc3[j]=0; }

            // h-part (cols 40..295): depends only on gate group's own h(t)
            #pragma unroll 2
            for (int c4 = 10; c4 < KG4; ++c4) GSTEP(c4);

            BARS(2, NT);    // wait z(t-1) + a(t) (pre-armed by MLP at t=0)

            // a+z part (cols 0..39)
            #pragma unroll 2
            for (int c4 = 0; c4 < 10; ++c4) GSTEP(c4);

            // cell; h(t+1) -> next buffer
            #pragma unroll
            for (int j = 0; j < 4; ++j) {
                float iv = fsig(hsum2(acc0[j]) + bs0);
                float fv = fsig(hsum2(acc1[j]) + bs1);
                float gv = ftanh_(hsum2(acc2[j]) + bs2);
                float ov = fsig(hsum2(acc3[j]) + bs3);
                float c = fv * c_reg[j] + iv * gv;
                c_reg[j] = c;
                xn[(bq * 4 + j) * KGP + 40 + hid] = ov * ftanh_(c);
            }
            BARA(1, NT);    // h(t+1) ready -> release MLP group
            BARS(3, 512);   // gate-internal: h writes visible for next h-part
        }
    } else {
        // ================= MLP GROUP (256 threads) =================
        const int t2 = tid - 512;
        const int mM = t2 & 127, q4 = (t2 >> 7) * 4;     // MLP rows q4..q4+3
        const int j64 = t2 & 63, u2r = (t2 >> 6) * 2;    // zz rows u2r, u2r+1
        const int jf = t2 & 31, rf = t2 >> 5;            // final z task
        const float b1v = b1[mM], b2v = b2[mM];
        const float bzv = bz[j64];

        BARA(2, NT);    // pre-arm Z: x(0) already holds z0 + a0

        for (int t = 0; t < TT; ++t) {
            float* xn = xh + ((t + 1) & 1) * 8 * KGP;

            BARS(1, NT);    // wait h(t+1)

            // a(t+1) prefetch
            if (t2 < 64 && t + 1 < TT) {
                int b = t2 >> 3, k = t2 & 7;
                xn[b * KGP + k] = A[((n0 + b) * TT + t + 1) * 8 + k];
            }

            // MLP1: output mM, rows q4..q4+3
            {
                ull a0=0, a1=0, a2=0, a3=0;
                const float* x0 = xn + q4 * KGP + 40;
                #pragma unroll 4
                for (int k4 = 0; k4 < 64; ++k4) {
                    const ulonglong2 wv = __ldg((const ulonglong2*)(W1_perm + ((k4 << 7) + mM) * 4));
                    const ulonglong2 p0 = *(const ulonglong2*)(x0 + 4 * k4);
                    const ulonglong2 p1 = *(const ulonglong2*)(x0 + KGP + 4 * k4);
                    const ulonglong2 p2 = *(const ulonglong2*)(x0 + 2 * KGP + 4 * k4);
                    const ulonglong2 p3 = *(const ulonglong2*)(x0 + 3 * KGP + 4 * k4);
                    fma2(a0, wv.x, p0.x); fma2(a0, wv.y, p0.y);
                    fma2(a1, wv.x, p1.x); fma2(a1, wv.y, p1.y);
                    fma2(a2, wv.x, p2.x); fma2(a2, wv.y, p2.y);
                    fma2(a3, wv.x, p3.x); fma2(a3, wv.y, p3.y);
                }
                u1s[q4 * US + mM]       = fmaxf(hsum2(a0) + b1v, 0.f);
                u1s[(q4 + 1) * US + mM] = fmaxf(hsum2(a1) + b1v, 0.f);
                u1s[(q4 + 2) * US + mM] = fmaxf(hsum2(a2) + b1v, 0.f);
                u1s[(q4 + 3) * US + mM] = fmaxf(hsum2(a3) + b1v, 0.f);
            }
            BARS(4, 256);

            // MLP2
            {
                ull a0=0, a1=0, a2=0, a3=0;
                const float* x0 = u1s + q4 * US;
                #pragma unroll 4
                for (int k4 = 0; k4 < 32; ++k4) {
                    const ulonglong2 wv = __ldg((const ulonglong2*)(W2_perm + ((k4 << 7) + mM) * 4));
                    const ulonglong2 p0 = *(const ulonglong2*)(x0 + 4 * k4);
                    const ulonglong2 p1 = *(const ulonglong2*)(x0 + US + 4 * k4);
                    const ulonglong2 p2 = *(const ulonglong2*)(x0 + 2 * US + 4 * k4);
                    const ulonglong2 p3 = *(const ulonglong2*)(x0 + 3 * US + 4 * k4);
                    fma2(a0, wv.x, p0.x); fma2(a0, wv.y, p0.y);
                    fma2(a1, wv.x, p1.x); fma2(a1, wv.y, p1.y);
                    fma2(a2, wv.x, p2.x); fma2(a2, wv.y, p2.y);
                    fma2(a3, wv.x, p3.x); fma2(a3, wv.y, p3.y);
                }
                u2s[q4 * US + mM]       = fmaxf(hsum2(a0) + b2v, 0.f);
                u2s[(q4 + 1) * US + mM] = fmaxf(hsum2(a1) + b2v, 0.f);
                u2s[(q4 + 2) * US + mM] = fmaxf(hsum2(a2) + b2v, 0.f);
                u2s[(q4 + 3) * US + mM] = fmaxf(hsum2(a3) + b2v, 0.f);
            }
            BARS(4, 256);

            // zz: output j64, rows u2r, u2r+1
            {
                ull a0 = 0, a1 = 0;
                const float* x0 = u2s + u2r * US;
                #pragma unroll 4
                for (int k4 = 0; k4 < 32; ++k4) {
                    const ulonglong2 wv = __ldg((const ulonglong2*)(Wz_perm + ((k4 << 6) + j64) * 4));
                    const ulonglong2 p0 = *(const ulonglong2*)(x0 + 4 * k4);
                    const ulonglong2 p1 = *(const ulonglong2*)(x0 + US + 4 * k4);
                    fma2(a0, wv.x, p0.x); fma2(a0, wv.y, p0.y);
                    fma2(a1, wv.x, p1.x); fma2(a1, wv.y, p1.y);
                }
                zzs[u2r * ZS + j64]       = hsum2(a0) + bzv;
                zzs[(u2r + 1) * ZS + j64] = hsum2(a1) + bzv;
            }
            BARS(4, 256);

            // z_t = loc + softplus(raw) * eps -> Z and xn z-cols
            {
                float loc = zzs[rf * ZS + jf];
                float sr  = zzs[rf * ZS + 32 + jf];
                float sp  = (sr > 15.f) ? sr : log1pf(__expf(sr));
                float e   = eps[((n0 + rf) * TT + t) * ZD + jf];
                float zn  = fmaf(sp, e, loc);
                Z[((n0 + rf) * TT + t) * ZD + jf] = zn;
                xn[rf * KGP + 8 + jf] = zn;
            }
            BARA(2, NT);    // z(t) + a(t+1) ready -> release gates
        }
    }
}

extern "C" void kernel_launch(void* const* d_in, const int* in_sizes, int n_in,
                              void* d_out, int out_size) {
    const float* A    = (const float*)d_in[0];
    const float* eps  = (const float*)d_in[1];
    const float* z0   = (const float*)d_in[2];
    const float* h0   = (const float*)d_in[3];
    const float* c0   = (const float*)d_in[4];
    const float* W_ih = (const float*)d_in[5];
    const float* W_hh = (const float*)d_in[6];
    const float* b_ih = (const float*)d_in[7];
    const float* b_hh = (const float*)d_in[8];
    const float* W1   = (const float*)d_in[9];
    const float* b1   = (const float*)d_in[10];
    const float* W2   = (const float*)d_in[11];
    const float* b2   = (const float*)d_in[12];
    const float* Wz   = (const float*)d_in[13];
    const float* bz   = (const float*)d_in[14];

    permute_weights<<<148, 256>>>(W_ih, W_hh, W1, W2, Wz);
    lstm_guide_kernel<<<128, NT>>>(A, eps, z0, h0, c0,
                                   b_ih, b_hh, b1, b2, bz, (float*)d_out);
}

// round 15
// speedup vs baseline: 1.6265x; 1.0004x over previous
#include <cuda_runtime.h>
typedef unsigned long long ull;

#define TT 128
#define ZD 32
#define KG4 74
#define KGP 300   // xh row stride (floats): a 0..7 | z 8..39 | h 40..295
#define US 132
#define ZS 68
#define NT 768    // 512 gate + 256 MLP

__device__ __align__(16) float Wg_perm[KG4 * 1024 * 4];  // [k4][1024 rows][4]
__device__ __align__(16) float W1_perm[64 * 128 * 4];
__device__ __align__(16) float W2_perm[32 * 128 * 4];
__device__ __align__(16) float Wz_perm[32 * 64 * 4];

__device__ __forceinline__ void fma2(ull &d, ull a, ull b) {
    asm("fma.rn.f32x2 %0, %1, %2, %0;" : "+l"(d) : "l"(a), "l"(b));
}
__device__ __forceinline__ float hsum2(ull v) {
    float lo, hi; asm("mov.b64 {%0, %1}, %2;" : "=f"(lo), "=f"(hi) : "l"(v));
    return lo + hi;
}
__device__ __forceinline__ float fsig(float x) { return 1.f / (1.f + __expf(-x)); }
__device__ __forceinline__ float ftanh_(float x) { return fmaf(2.f, fsig(2.f * x), -1.f); }

#define BARS(id, cnt) asm volatile("bar.sync %0, %1;"   :: "r"(id), "r"(cnt) : "memory")
#define BARA(id, cnt) asm volatile("bar.arrive %0, %1;" :: "r"(id), "r"(cnt) : "memory")
// ids: 1=H (h ready; gates arrive, MLP sync), 2=Z (z+a ready; MLP arrive, gates sync),
//      3=gate-internal, 4=MLP-internal

__global__ void permute_weights(const float* __restrict__ W_ih, const float* __restrict__ W_hh,
                                const float* __restrict__ W1, const float* __restrict__ W2,
                                const float* __restrict__ Wz)
{
    const int stride = gridDim.x * blockDim.x;
    const int tid = blockIdx.x * blockDim.x + threadIdx.x;
    for (int i = tid; i < KG4 * 1024 * 4; i += stride) {
        int j = i & 3, R = (i >> 2) & 1023, k4 = i >> 12;
        int k = 4 * k4 + j;
        Wg_perm[i] = (k < 40) ? W_ih[R * 40 + k] : W_hh[R * 256 + (k - 40)];
    }
    for (int i = tid; i < 64 * 128 * 4; i += stride) {
        int j = i & 3, m = (i >> 2) & 127, k4 = i >> 9;
        W1_perm[i] = W1[m * 256 + 4 * k4 + j];
    }
    for (int i = tid; i < 32 * 128 * 4; i += stride) {
        int j = i & 3, m = (i >> 2) & 127, k4 = i >> 9;
        W2_perm[i] = W2[m * 128 + 4 * k4 + j];
    }
    for (int i = tid; i < 32 * 64 * 4; i += stride) {
        int j = i & 3, m = (i >> 2) & 63, k4 = i >> 8;
        Wz_perm[i] = Wz[m * 128 + 4 * k4 + j];
    }
}

#define GSTEP(c4) do { \
    const ulonglong2 w0 = __ldg((const ulonglong2*)(wb + ((c4) * 1024 +   0) * 4)); \
    const ulonglong2 w1 = __ldg((const ulonglong2*)(wb + ((c4) * 1024 + 256) * 4)); \
    const ulonglong2 w2 = __ldg((const ulonglong2*)(wb + ((c4) * 1024 + 512) * 4)); \
    const ulonglong2 w3 = __ldg((const ulonglong2*)(wb + ((c4) * 1024 + 768) * 4)); \
    _Pragma("unroll") \
    for (int j = 0; j < 4; ++j) { \
        const ulonglong2 xv = *(const ulonglong2*)(xc + (bq * 4 + j) * KGP + 4 * (c4)); \
        fma2(acc0[j], w0.x, xv.x); fma2(acc0[j], w0.y, xv.y); \
        fma2(acc1[j], w1.x, xv.x); fma2(acc1[j], w1.y, xv.y); \
        fma2(acc2[j], w2.x, xv.x); fma2(acc2[j], w2.y, xv.y); \
        fma2(acc3[j], w3.x, xv.x); fma2(acc3[j], w3.y, xv.y); \
    } \
} while (0)

// 768 threads: tid<512 = gate group (hid=tid>>1, bq=tid&1: 4 gates x 4 batch,
// round-7 tile, no spills). tid>=512 = MLP group (full chain + a-prefetch).
// Gates overlap the h-part of step t with the MLP chain of step t-1.
__global__ void __launch_bounds__(NT, 1)
lstm_guide_kernel(const float* __restrict__ A, const float* __restrict__ eps,
                  const float* __restrict__ z0, const float* __restrict__ h0,
                  const float* __restrict__ c0, const float* __restrict__ b_ih,
                  const float* __restrict__ b_hh, const float* __restrict__ b1,
                  const float* __restrict__ b2, const float* __restrict__ bz,
                  float* __restrict__ Z)
{
    __shared__ __align__(16) float xh[2 * 8 * KGP];
    __shared__ __align__(16) float u1s[8 * US];
    __shared__ __align__(16) float u2s[8 * US];
    __shared__ __align__(16) float zzs[8 * ZS];

    const int tid = threadIdx.x;
    const int n0 = blockIdx.x * 8;

    // ---- init x(0) = [a0 | z0 | h0] into buffer 0 ----
    for (int i = tid; i < 8 * 256; i += NT) {
        int b = i >> 8, k = i & 255;
        xh[b * KGP + 40 + k] = h0[k];
    }
    if (tid < 64) {
        int b = tid >> 3, k = tid & 7;
        xh[b * KGP + k] = A[((n0 + b) * TT) * 8 + k];
    } else if (tid < 320) {
        int i = tid - 64, b = i >> 5, j = i & 31;
        xh[b * KGP + 8 + j] = z0[j];
    }
    __syncthreads();

    if (tid < 512) {
        // ================= GATE GROUP (512 threads) =================
        const int hid = tid >> 1, bq = tid & 1;
        const float bs0 = b_ih[hid]       + b_hh[hid];
        const float bs1 = b_ih[256 + hid] + b_hh[256 + hid];
        const float bs2 = b_ih[512 + hid] + b_hh[512 + hid];
        const float bs3 = b_ih[768 + hid] + b_hh[768 + hid];
        const float* wb = Wg_perm + hid * 4;
        float c_reg[4];
        #pragma unroll
        for (int j = 0; j < 4; ++j) c_reg[j] = c0[hid];

        for (int t = 0; t < TT; ++t) {
            const float* xc = xh + (t & 1) * 8 * KGP;
            float* xn = xh + ((t + 1) & 1) * 8 * KGP;

            ull acc0[4], acc1[4], acc2[4], acc3[4];
            #pragma unroll
            for (int j = 0; j < 4; ++j) { acc0[j]=0; acc1[j]=0; acc2[j]=0; acc3[j]=0; }

            // h-part (cols 40..295): depends only on gate group's own h(t)
            #pragma unroll 2
            for (int c4 = 10; c4 < KG4; ++c4) GSTEP(c4);

            BARS(2, NT);    // wait z(t-1) + a(t) (pre-armed by MLP at t=0)

            // a+z part (cols 0..39)
            #pragma unroll 2
            for (int c4 = 0; c4 < 10; ++c4) GSTEP(c4);

            // cell; h(t+1) -> next buffer
            #pragma unroll
            for (int j = 0; j < 4; ++j) {
                float iv = fsig(hsum2(acc0[j]) + bs0);
                float fv = fsig(hsum2(acc1[j]) + bs1);
                float gv = ftanh_(hsum2(acc2[j]) + bs2);
                float ov = fsig(hsum2(acc3[j]) + bs3);
                float c = fv * c_reg[j] + iv * gv;
                c_reg[j] = c;
                xn[(bq * 4 + j) * KGP + 40 + hid] = ov * ftanh_(c);
            }
            BARA(1, NT);    // h(t+1) ready -> release MLP group
            BARS(3, 512);   // gate-internal: h writes visible for next h-part
        }
    } else {
        // ================= MLP GROUP (256 threads) =================
        const int t2 = tid - 512;
        const int mM = t2 & 127, q4 = (t2 >> 7) * 4;     // MLP rows q4..q4+3
        const int j64 = t2 & 63, u2r = (t2 >> 6) * 2;    // zz rows u2r, u2r+1
        const int jf = t2 & 31, rf = t2 >> 5;            // final z task
        const float b1v = b1[mM], b2v = b2[mM];
        const float bzv = bz[j64];

        BARA(2, NT);    // pre-arm Z: x(0) already holds z0 + a0

        for (int t = 0; t < TT; ++t) {
            float* xn = xh + ((t + 1) & 1) * 8 * KGP;

            BARS(1, NT);    // wait h(t+1)

            // a(t+1) prefetch
            if (t2 < 64 && t + 1 < TT) {
                int b = t2 >> 3, k = t2 & 7;
                xn[b * KGP + k] = A[((n0 + b) * TT + t + 1) * 8 + k];
            }

            // MLP1: output mM, rows q4..q4+3
            {
                ull a0=0, a1=0, a2=0, a3=0;
                const float* x0 = xn + q4 * KGP + 40;
                #pragma unroll 4
                for (int k4 = 0; k4 < 64; ++k4) {
                    const ulonglong2 wv = __ldg((const ulonglong2*)(W1_perm + ((k4 << 7) + mM) * 4));
                    const ulonglong2 p0 = *(const ulonglong2*)(x0 + 4 * k4);
                    const ulonglong2 p1 = *(const ulonglong2*)(x0 + KGP + 4 * k4);
                    const ulonglong2 p2 = *(const ulonglong2*)(x0 + 2 * KGP + 4 * k4);
                    const ulonglong2 p3 = *(const ulonglong2*)(x0 + 3 * KGP + 4 * k4);
                    fma2(a0, wv.x, p0.x); fma2(a0, wv.y, p0.y);
                    fma2(a1, wv.x, p1.x); fma2(a1, wv.y, p1.y);
                    fma2(a2, wv.x, p2.x); fma2(a2, wv.y, p2.y);
                    fma2(a3, wv.x, p3.x); fma2(a3, wv.y, p3.y);
                }
                u1s[q4 * US + mM]       = fmaxf(hsum2(a0) + b1v, 0.f);
                u1s[(q4 + 1) * US + mM] = fmaxf(hsum2(a1) + b1v, 0.f);
                u1s[(q4 + 2) * US + mM] = fmaxf(hsum2(a2) + b1v, 0.f);
                u1s[(q4 + 3) * US + mM] = fmaxf(hsum2(a3) + b1v, 0.f);
            }
            BARS(4, 256);

            // MLP2
            {
                ull a0=0, a1=0, a2=0, a3=0;
                const float* x0 = u1s + q4 * US;
                #pragma unroll 4
                for (int k4 = 0; k4 < 32; ++k4) {
                    const ulonglong2 wv = __ldg((const ulonglong2*)(W2_perm + ((k4 << 7) + mM) * 4));
                    const ulonglong2 p0 = *(const ulonglong2*)(x0 + 4 * k4);
                    const ulonglong2 p1 = *(const ulonglong2*)(x0 + US + 4 * k4);
                    const ulonglong2 p2 = *(const ulonglong2*)(x0 + 2 * US + 4 * k4);
                    const ulonglong2 p3 = *(const ulonglong2*)(x0 + 3 * US + 4 * k4);
                    fma2(a0, wv.x, p0.x); fma2(a0, wv.y, p0.y);
                    fma2(a1, wv.x, p1.x); fma2(a1, wv.y, p1.y);
                    fma2(a2, wv.x, p2.x); fma2(a2, wv.y, p2.y);
                    fma2(a3, wv.x, p3.x); fma2(a3, wv.y, p3.y);
                }
                u2s[q4 * US + mM]       = fmaxf(hsum2(a0) + b2v, 0.f);
                u2s[(q4 + 1) * US + mM] = fmaxf(hsum2(a1) + b2v, 0.f);
                u2s[(q4 + 2) * US + mM] = fmaxf(hsum2(a2) + b2v, 0.f);
                u2s[(q4 + 3) * US + mM] = fmaxf(hsum2(a3) + b2v, 0.f);
            }
            BARS(4, 256);

            // zz: output j64, rows u2r, u2r+1
            {
                ull a0 = 0, a1 = 0;
                const float* x0 = u2s + u2r * US;
                #pragma unroll 4
                for (int k4 = 0; k4 < 32; ++k4) {
                    const ulonglong2 wv = __ldg((const ulonglong2*)(Wz_perm + ((k4 << 6) + j64) * 4));
                    const ulonglong2 p0 = *(const ulonglong2*)(x0 + 4 * k4);
                    const ulonglong2 p1 = *(const ulonglong2*)(x0 + US + 4 * k4);
                    fma2(a0, wv.x, p0.x); fma2(a0, wv.y, p0.y);
                    fma2(a1, wv.x, p1.x); fma2(a1, wv.y, p1.y);
                }
                zzs[u2r * ZS + j64]       = hsum2(a0) + bzv;
                zzs[(u2r + 1) * ZS + j64] = hsum2(a1) + bzv;
            }
            BARS(4, 256);

            // z_t = loc + softplus(raw) * eps -> Z and xn z-cols
            {
                float loc = zzs[rf * ZS + jf];
                float sr  = zzs[rf * ZS + 32 + jf];
                float sp  = (sr > 15.f) ? sr : log1pf(__expf(sr));
                float e   = eps[((n0 + rf) * TT + t) * ZD + jf];
                float zn  = fmaf(sp, e, loc);
                Z[((n0 + rf) * TT + t) * ZD + jf] = zn;
                xn[rf * KGP + 8 + jf] = zn;
            }
            BARA(2, NT);    // z(t) + a(t+1) ready -> release gates
        }
    }
}

extern "C" void kernel_launch(void* const* d_in, const int* in_sizes, int n_in,
                              void* d_out, int out_size) {
    const float* A    = (const float*)d_in[0];
    const float* eps  = (const float*)d_in[1];
    const float* z0   = (const float*)d_in[2];
    const float* h0   = (const float*)d_in[3];
    const float* c0   = (const float*)d_in[4];
    const float* W_ih = (const float*)d_in[5];
    const float* W_hh = (const float*)d_in[6];
    const float* b_ih = (const float*)d_in[7];
    const float* b_hh = (const float*)d_in[8];
    const float* W1   = (const float*)d_in[9];
    const float* b1   = (const float*)d_in[10];
    const float* W2   = (const float*)d_in[11];
    const float* b2   = (const float*)d_in[12];
    const float* Wz   = (const float*)d_in[13];
    const float* bz   = (const float*)d_in[14];

    permute_weights<<<148, 256>>>(W_ih, W_hh, W1, W2, Wz);
    lstm_guide_kernel<<<128, NT>>>(A, eps, z0, h0, c0,
                                   b_ih, b_hh, b1, b2, bz, (float*)d_out);
}

// round 17
// speedup vs baseline: 2.8695x; 1.7642x over previous
#include <cuda_runtime.h>
#include <cuda_bf16.h>
#include <cstdint>
typedef unsigned long long ull;
typedef unsigned int u32;
typedef __nv_bfloat16 bf16;

#define TT 128
#define ZD 32
#define XBS 312            // xb row stride (bf16): a 0..7 | z 8..39 | h 40..295 | pad
#define XHS 256
#define US 132
#define ZS 68
#define NT 512

// dynamic smem byte offsets
#define O_XB   0           // 16 x 312 bf16 = 9984
#define O_XH   9984        // 8 x 256 fp32 = 8192
#define O_GSUM 18176       // 1024 x 8 fp32 = 32768 (u1s/u2s/zzs overlaid)
#define O_U1   18176
#define O_U2   (O_U1 + 8*US*4)
#define O_ZZ   (O_U2 + 8*US*4)
#define SMEMB  50944

__device__ __align__(16) bf16 Wfrag[19 * 64 * 32 * 8];   // [kt][mt][lane][8]
__device__ __align__(16) float W1_perm[64 * 128 * 4];
__device__ __align__(16) float W2_perm[32 * 128 * 4];
__device__ __align__(16) float Wz_perm[32 * 64 * 4];

__device__ __forceinline__ void fma2(ull &d, ull a, ull b) {
    asm("fma.rn.f32x2 %0, %1, %2, %0;" : "+l"(d) : "l"(a), "l"(b));
}
__device__ __forceinline__ float hsum2(ull v) {
    float lo, hi; asm("mov.b64 {%0, %1}, %2;" : "=f"(lo), "=f"(hi) : "l"(v));
    return lo + hi;
}
__device__ __forceinline__ float fsig(float x) { return 1.f / (1.f + __expf(-x)); }
__device__ __forceinline__ float ftanh_(float x) { return fmaf(2.f, fsig(2.f * x), -1.f); }

__device__ __forceinline__ void mma16816(float* d, uint4 a, u32 b0, u32 b1) {
    asm volatile("mma.sync.aligned.m16n8k16.row.col.f32.bf16.bf16.f32 "
        "{%0,%1,%2,%3}, {%4,%5,%6,%7}, {%8,%9}, {%0,%1,%2,%3};"
        : "+f"(d[0]), "+f"(d[1]), "+f"(d[2]), "+f"(d[3])
        : "r"(a.x), "r"(a.y), "r"(a.z), "r"(a.w), "r"(b0), "r"(b1));
}
// activation write: hi in row b, residual in row b+8 (exact split)
__device__ __forceinline__ void xput(bf16* xb, int b, int k, float v) {
    bf16 hi = __float2bfloat16(v);
    xb[b * XBS + k] = hi;
    xb[(b + 8) * XBS + k] = __float2bfloat16(v - __bfloat162float(hi));
}

__device__ __forceinline__ float gw(const float* W_ih, const float* W_hh, int m, int k) {
    if (k < 40)  return W_ih[m * 40 + k];
    if (k < 296) return W_hh[m * 256 + (k - 40)];
    return 0.f;
}

__global__ void prep(const float* __restrict__ W_ih, const float* __restrict__ W_hh,
                     const float* __restrict__ W1, const float* __restrict__ W2,
                     const float* __restrict__ Wz)
{
    const int st = gridDim.x * blockDim.x, tid = blockIdx.x * blockDim.x + threadIdx.x;
    for (int i = tid; i < 19 * 64 * 32; i += st) {       // one 16B fragment slot
        int kt = i / (64 * 32), r = i % (64 * 32), mt = r >> 5, ln = r & 31;
        int g = ln >> 2, tq = ln & 3;
        int m0 = mt * 16 + g, k0 = kt * 16 + 2 * tq;
        bf16* p = Wfrag + (size_t)i * 8;
        p[0] = __float2bfloat16(gw(W_ih, W_hh, m0,     k0));
        p[1] = __float2bfloat16(gw(W_ih, W_hh, m0,     k0 + 1));
        p[2] = __float2bfloat16(gw(W_ih, W_hh, m0 + 8, k0));
        p[3] = __float2bfloat16(gw(W_ih, W_hh, m0 + 8, k0 + 1));
        p[4] = __float2bfloat16(gw(W_ih, W_hh, m0,     k0 + 8));
        p[5] = __float2bfloat16(gw(W_ih, W_hh, m0,     k0 + 9));
        p[6] = __float2bfloat16(gw(W_ih, W_hh, m0 + 8, k0 + 8));
        p[7] = __float2bfloat16(gw(W_ih, W_hh, m0 + 8, k0 + 9));
    }
    for (int i = tid; i < 64 * 128 * 4; i += st) {
        int j = i & 3, m = (i >> 2) & 127, k4 = i >> 9;
        W1_perm[i] = W1[m * 256 + 4 * k4 + j];
    }
    for (int i = tid; i < 32 * 128 * 4; i += st) {
        int j = i & 3, m = (i >> 2) & 127, k4 = i >> 9;
        W2_perm[i] = W2[m * 128 + 4 * k4 + j];
    }
    for (int i = tid; i < 32 * 64 * 4; i += st) {
        int j = i & 3, m = (i >> 2) & 63, k4 = i >> 8;
        Wz_perm[i] = Wz[m * 128 + 4 * k4 + j];
    }
}

__global__ void __launch_bounds__(NT, 1)
lstm_mma_kernel(const float* __restrict__ A, const float* __restrict__ eps,
                const float* __restrict__ z0, const float* __restrict__ h0,
                const float* __restrict__ c0, const float* __restrict__ b_ih,
                const float* __restrict__ b_hh, const float* __restrict__ b1,
                const float* __restrict__ b2, const float* __restrict__ bz,
                float* __restrict__ Z)
{
    extern __shared__ __align__(16) char sm[];
    bf16*  xb   = (bf16*)(sm + O_XB);
    float* xh   = (float*)(sm + O_XH);
    float* gsum = (float*)(sm + O_GSUM);
    float* u1s  = (float*)(sm + O_U1);
    float* u2s  = (float*)(sm + O_U2);
    float* zzs  = (float*)(sm + O_ZZ);

    const int tid = threadIdx.x, w = tid >> 5, ln = tid & 31;
    const int g = ln >> 2, tq = ln & 3;
    const int n0 = blockIdx.x * 8;
    const int hid = tid >> 1, bq = tid & 1;

    const float bs0 = b_ih[hid]       + b_hh[hid];
    const float bs1 = b_ih[256 + hid] + b_hh[256 + hid];
    const float bs2 = b_ih[512 + hid] + b_hh[512 + hid];
    const float bs3 = b_ih[768 + hid] + b_hh[768 + hid];
    const float b1v = b1[tid & 127], b2v = b2[tid & 127], bzv = bz[tid & 63];

    // init xb (zero incl. pad), then x(0) = [a0|z0|h0]; c from c0
    for (int i = tid; i < 16 * XBS / 2; i += NT) ((u32*)xb)[i] = 0;
    __syncthreads();
    for (int i = tid; i < 8 * 256; i += NT) xput(xb, i >> 8, 40 + (i & 255), h0[i & 255]);
    for (int i = tid; i < 8 * 32; i += NT)  xput(xb, i >> 5, 8 + (i & 31), z0[i & 31]);
    if (tid < 64) xput(xb, tid >> 3, tid & 7, A[((n0 + (tid >> 3)) * TT) * 8 + (tid & 7)]);
    float c_reg[4];
    #pragma unroll
    for (int j = 0; j < 4; ++j) c_reg[j] = c0[hid];
    __syncthreads();

    for (int t = 0; t < TT; ++t) {
        // ===== gates on HMMA: warp w owns M-tiles w*4..w*4+3 =====
        float dh[4][4], dl[4][4];
        #pragma unroll
        for (int i = 0; i < 4; ++i)
            #pragma unroll
            for (int j = 0; j < 4; ++j) { dh[i][j] = 0.f; dl[i][j] = 0.f; }

        #pragma unroll 1
        for (int kt = 0; kt < 19; ++kt) {
            const int kb = kt * 16 + 2 * tq;
            const u32 bh0 = *(const u32*)&xb[g * XBS + kb];
            const u32 bh1 = *(const u32*)&xb[g * XBS + kb + 8];
            const u32 bl0 = *(const u32*)&xb[(g + 8) * XBS + kb];
            const u32 bl1 = *(const u32*)&xb[(g + 8) * XBS + kb + 8];
            #pragma unroll
            for (int i = 0; i < 4; ++i) {
                const uint4 a = __ldg((const uint4*)Wfrag + (kt * 64 + w * 4 + i) * 32 + ln);
                mma16816(dh[i], a, bh0, bh1);
                mma16816(dl[i], a, bl0, bl1);
            }
        }
        #pragma unroll
        for (int i = 0; i < 4; ++i) {     // gsum[m][b] = hi + lo
            const int m0 = (w * 4 + i) * 16 + g;
            float2 v0 = { dh[i][0] + dl[i][0], dh[i][1] + dl[i][1] };
            float2 v1 = { dh[i][2] + dl[i][2], dh[i][3] + dl[i][3] };
            *(float2*)(gsum + m0 * 8 + 2 * tq) = v0;
            *(float2*)(gsum + (m0 + 8) * 8 + 2 * tq) = v1;
        }
        __syncthreads();

        // ===== LSTM cell: thread (hid, bq) handles batches bq*4..+3 =====
        {
            const float4 gi = *(const float4*)(gsum + hid * 8 + bq * 4);
            const float4 gf = *(const float4*)(gsum + (256 + hid) * 8 + bq * 4);
            const float4 gg = *(const float4*)(gsum + (512 + hid) * 8 + bq * 4);
            const float4 go = *(const float4*)(gsum + (768 + hid) * 8 + bq * 4);
            const float iv[4] = { gi.x, gi.y, gi.z, gi.w };
            const float fv[4] = { gf.x, gf.y, gf.z, gf.w };
            const float gv[4] = { gg.x, gg.y, gg.z, gg.w };
            const float ov[4] = { go.x, go.y, go.z, go.w };
            #pragma unroll
            for (int j = 0; j < 4; ++j) {
                float c = fsig(fv[j] + bs1) * c_reg[j]
                        + fsig(iv[j] + bs0) * ftanh_(gv[j] + bs2);
                c_reg[j] = c;
                float h = fsig(ov[j] + bs3) * ftanh_(c);
                xh[(bq * 4 + j) * XHS + hid] = h;
                xput(xb, bq * 4 + j, 40 + hid, h);
            }
        }
        if (tid < 64 && t + 1 < TT) {     // a(t+1)
            int b = tid >> 3, k = tid & 7;
            xput(xb, b, k, A[((n0 + b) * TT + t + 1) * 8 + k]);
        }
        __syncthreads();

        // ===== MLP1 (fp32 SIMT, round-7 form) =====
        {
            const int m = tid & 127, q = tid >> 7;
            const float* x0 = xh + (2 * q) * XHS;
            const float* x1 = x0 + XHS;
            ull a0 = 0, a1 = 0;
            #pragma unroll 4
            for (int k4 = 0; k4 < 64; ++k4) {
                const ulonglong2 wv = __ldg((const ulonglong2*)(W1_perm + ((k4 << 7) + m) * 4));
                const ulonglong2 p0 = *(const ulonglong2*)(x0 + 4 * k4);
                const ulonglong2 p1 = *(const ulonglong2*)(x1 + 4 * k4);
                fma2(a0, wv.x, p0.x); fma2(a0, wv.y, p0.y);
                fma2(a1, wv.x, p1.x); fma2(a1, wv.y, p1.y);
            }
            u1s[(2 * q) * US + m]     = fmaxf(hsum2(a0) + b1v, 0.f);
            u1s[(2 * q + 1) * US + m] = fmaxf(hsum2(a1) + b1v, 0.f);
        }
        __syncthreads();
        // ===== MLP2 =====
        {
            const int m = tid & 127, q = tid >> 7;
            const float* x0 = u1s + (2 * q) * US;
            const float* x1 = x0 + US;
            ull a0 = 0, a1 = 0;
            #pragma unroll 4
            for (int k4 = 0; k4 < 32; ++k4) {
                const ulonglong2 wv = __ldg((const ulonglong2*)(W2_perm + ((k4 << 7) + m) * 4));
                const ulonglong2 p0 = *(const ulonglong2*)(x0 + 4 * k4);
                const ulonglong2 p1 = *(const ulonglong2*)(x1 + 4 * k4);
                fma2(a0, wv.x, p0.x); fma2(a0, wv.y, p0.y);
                fma2(a1, wv.x, p1.x); fma2(a1, wv.y, p1.y);
            }
            u2s[(2 * q) * US + m]     = fmaxf(hsum2(a0) + b2v, 0.f);
            u2s[(2 * q + 1) * US + m] = fmaxf(hsum2(a1) + b2v, 0.f);
        }
        __syncthreads();
        // ===== zz =====
        {
            const int jz = tid & 63, rz = tid >> 6;
            const float* xp = u2s + rz * US;
            ull a0 = 0;
            #pragma unroll 4
            for (int k4 = 0; k4 < 32; ++k4) {
                const ulonglong2 wv = __ldg((const ulonglong2*)(Wz_perm + ((k4 << 6) + jz) * 4));
                const ulonglong2 pv = *(const ulonglong2*)(xp + 4 * k4);
                fma2(a0, wv.x, pv.x); fma2(a0, wv.y, pv.y);
            }
            zzs[rz * ZS + jz] = hsum2(a0) + bzv;
        }
        __syncthreads();
        // ===== z =====
        if (tid < 256) {
            const int j = tid & 31, r = tid >> 5;
            float loc = zzs[r * ZS + j];
            float sr  = zzs[r * ZS + 32 + j];
            float sp  = (sr > 15.f) ? sr : log1pf(__expf(sr));
            float e   = eps[((n0 + r) * TT + t) * ZD + j];
            float zn  = fmaf(sp, e, loc);
            Z[((n0 + r) * TT + t) * ZD + j] = zn;
            xput(xb, r, 8 + j, zn);
        }
        __syncthreads();
    }
}

extern "C" void kernel_launch(void* const* d_in, const int* in_sizes, int n_in,
                              void* d_out, int out_size) {
    const float* A    = (const float*)d_in[0];
    const float* eps  = (const float*)d_in[1];
    const float* z0   = (const float*)d_in[2];
    const float* h0   = (const float*)d_in[3];
    const float* c0   = (const float*)d_in[4];
    const float* W_ih = (const float*)d_in[5];
    const float* W_hh = (const float*)d_in[6];
    const float* b_ih = (const float*)d_in[7];
    const float* b_hh = (const float*)d_in[8];
    const float* W1   = (const float*)d_in[9];
    const float* b1   = (const float*)d_in[10];
    const float* W2   = (const float*)d_in[11];
    const float* b2   = (const float*)d_in[12];
    const float* Wz   = (const float*)d_in[13];
    const float* bz   = (const float*)d_in[14];

    static int once = 0;
    if (!once) {
        cudaFuncSetAttribute(lstm_mma_kernel, cudaFuncAttributeMaxDynamicSharedMemorySize, SMEMB);
        once = 1;
    }
    prep<<<148, 256>>>(W_ih, W_hh, W1, W2, Wz);
    lstm_mma_kernel<<<128, NT, SMEMB>>>(A, eps, z0, h0, c0,
                                        b_ih, b_hh, b1, b2, bz, (float*)d_out);
}